// round 13
// baseline (speedup 1.0000x reference)
#include <cuda_runtime.h>
#include <limits.h>

#define N_NODES 100000
#define TPB     256
#define EPS     1e-16f
#define SCAN_BLK 1024
#define NB 98   // ceil(100000/1024)

// ---------------- scratch (device globals; alloc-free) ----------------
__device__ float g_q[N_NODES * 32];
__device__ float g_k[N_NODES * 32];
__device__ float g_v[N_NODES * 32];
__device__ float g_s[N_NODES * 32];
__device__ float g_sum[N_NODES];
__device__ float g_agg[N_NODES * 32];
// sorted edge list (by dst)
__device__ int g_deg[N_NODES];
__device__ int g_start[N_NODES];
__device__ int g_cur[N_NODES];
__device__ int g_srcs[1700000];
__device__ int g_dsts[1700000];
__device__ int g_bsum[NB];

// ---------------- sort-by-dst build ----------------
__global__ void zero_deg() {
    int i = blockIdx.x * blockDim.x + threadIdx.x;
    if (i < N_NODES) g_deg[i] = 0;
}

__global__ void hist(const int* __restrict__ ei, int E) {
    int e = blockIdx.x * blockDim.x + threadIdx.x;
    if (e < E) atomicAdd(&g_deg[__ldg(ei + E + e)], 1);
}

__global__ void scanA() {
    __shared__ int wsum[32];
    int t = threadIdx.x, lane = t & 31, wid = t >> 5;
    int i = blockIdx.x * SCAN_BLK + t;
    int v = (i < N_NODES) ? g_deg[i] : 0;
    int incl = v;
#pragma unroll
    for (int off = 1; off < 32; off <<= 1) {
        int n = __shfl_up_sync(0xffffffffu, incl, off);
        if (lane >= off) incl += n;
    }
    if (lane == 31) wsum[wid] = incl;
    __syncthreads();
    if (wid == 0) {
        int w = wsum[lane];
#pragma unroll
        for (int off = 1; off < 32; off <<= 1) {
            int n = __shfl_up_sync(0xffffffffu, w, off);
            if (lane >= off) w += n;
        }
        wsum[lane] = w;
    }
    __syncthreads();
    int woff = (wid > 0) ? wsum[wid - 1] : 0;
    incl += woff;
    if (i < N_NODES) g_start[i] = incl - v;
    if (t == SCAN_BLK - 1) g_bsum[blockIdx.x] = incl;
}

// scanC: block offset = sum of g_bsum[j < blockIdx] via smem reduction
// (R9-proven fold of scanB into scanC)
__global__ void scanC() {
    __shared__ int boff;
    if (threadIdx.x == 0) boff = 0;
    __syncthreads();
    if (threadIdx.x < (unsigned)blockIdx.x) atomicAdd(&boff, g_bsum[threadIdx.x]);
    __syncthreads();
    int i = blockIdx.x * SCAN_BLK + threadIdx.x;
    if (i < N_NODES) g_cur[i] = g_start[i] + boff;
}

__global__ void scatter(const int* __restrict__ ei, int E) {
    int e = blockIdx.x * blockDim.x + threadIdx.x;
    if (e >= E) return;
    int s = __ldg(ei + e);
    int d = __ldg(ei + E + e);
    int pos = atomicAdd(&g_cur[d], 1);
    g_srcs[pos] = s;
    g_dsts[pos] = d;
}

// ---------------- layer-1 transform + zero agg/sum ----------------
__global__ void xform1(const float* __restrict__ x,
                       const float* __restrict__ Wq, const float* __restrict__ bq,
                       const float* __restrict__ Wk, const float* __restrict__ bk,
                       const float* __restrict__ Wv, const float* __restrict__ bv,
                       const float* __restrict__ Ws, const float* __restrict__ bs) {
    __shared__ float sWq[32 * 32], sWk[32 * 32], sWv[32 * 32], sWs[32 * 32];
    __shared__ float sB[4 * 32];
    for (int i = threadIdx.x; i < 32 * 32; i += blockDim.x) {
        sWq[i] = Wq[i]; sWk[i] = Wk[i]; sWv[i] = Wv[i]; sWs[i] = Ws[i];
    }
    for (int i = threadIdx.x; i < 32; i += blockDim.x) {
        sB[i] = bq[i]; sB[32 + i] = bk[i]; sB[64 + i] = bv[i]; sB[96 + i] = bs[i];
    }
    __syncthreads();

    int lane = threadIdx.x & 31;
    int node = (blockIdx.x * blockDim.x + threadIdx.x) >> 5;
    if (node >= N_NODES) return;

    float xv = x[node * 32 + lane];
    float aq = 0.f, ak = 0.f, av = 0.f, as_ = 0.f;
#pragma unroll
    for (int kk = 0; kk < 32; kk++) {
        float xk = __shfl_sync(0xffffffffu, xv, kk);
        aq  += xk * sWq[kk * 32 + lane];
        ak  += xk * sWk[kk * 32 + lane];
        av  += xk * sWv[kk * 32 + lane];
        as_ += xk * sWs[kk * 32 + lane];
    }
    int o = node * 32 + lane;
    g_q[o] = aq  + sB[lane];
    g_k[o] = ak  + sB[32 + lane];
    g_v[o] = av  + sB[64 + lane];
    g_s[o] = as_ + sB[96 + lane];
    g_agg[o] = 0.f;
    if (lane == 0) g_sum[node] = 0.f;
}

// ---------------- segmented edge reduce over dst-sorted edges --------------
// G = D/4 lanes per edge group; each group walks CHUNK consecutive sorted
// edges, accumulating while dst unchanged, flushing with float4 atomics on
// run boundaries.  Loop trip count uniform across warp -> full-mask shfls OK.
template <int D, int CHUNK>
__global__ void edge_seg(int E, float rscale) {
    constexpr int G  = D / 4;
    constexpr int NG = 32 / G;
    int lane = threadIdx.x & 31;
    int wid  = threadIdx.x >> 5;
    int grp  = lane / G;
    int sub  = lane % G;

    int base = (((blockIdx.x * 8 + wid) * NG) + grp) * CHUNK;

    float4 acc = make_float4(0.f, 0.f, 0.f, 0.f);
    float  wsum = 0.f;
    int    prev_d = -1;
    float4 qv = make_float4(0.f, 0.f, 0.f, 0.f);

    for (int it = 0; it < CHUNK; it++) {
        int e = base + it;
        bool valid = (e < E);
        int d = valid ? __ldg(g_dsts + e) : prev_d;
        int s = valid ? __ldg(g_srcs + e) : 0;

        if (d != prev_d) {
            if (prev_d >= 0) {
                atomicAdd(reinterpret_cast<float4*>(g_agg + prev_d * D + sub * 4), acc);
                if (sub == 0) atomicAdd(&g_sum[prev_d], wsum);
            }
            acc = make_float4(0.f, 0.f, 0.f, 0.f);
            wsum = 0.f;
            prev_d = d;
            qv = *reinterpret_cast<const float4*>(g_q + d * D + sub * 4);
        }

        const float4 kv = *reinterpret_cast<const float4*>(g_k + s * D + sub * 4);
        float p = qv.x * kv.x + qv.y * kv.y + qv.z * kv.z + qv.w * kv.w;
#pragma unroll
        for (int off = 1; off < G; off <<= 1)
            p += __shfl_xor_sync(0xffffffffu, p, off);
        float w = valid ? __expf(fminf(p * rscale, 85.0f)) : 0.f;
        wsum += w;
        const float4 vv = *reinterpret_cast<const float4*>(g_v + s * D + sub * 4);
        acc.x += w * vv.x; acc.y += w * vv.y; acc.z += w * vv.z; acc.w += w * vv.w;
    }
    if (prev_d >= 0) {
        atomicAdd(reinterpret_cast<float4*>(g_agg + prev_d * D + sub * 4), acc);
        if (sub == 0) atomicAdd(&g_sum[prev_d], wsum);
    }
}

// ---------------- finish layer 1 + layer-2 transform + re-zero -------------
__global__ void finish1_xform2(const float* __restrict__ Wq, const float* __restrict__ bq,
                               const float* __restrict__ Wk, const float* __restrict__ bk,
                               const float* __restrict__ Wv, const float* __restrict__ bv,
                               const float* __restrict__ Ws, const float* __restrict__ bs) {
    __shared__ float sWq[32 * 16], sWk[32 * 16], sWv[32 * 16], sWs[32 * 16];
    __shared__ float sB[4 * 16];
    for (int i = threadIdx.x; i < 32 * 16; i += blockDim.x) {
        sWq[i] = Wq[i]; sWk[i] = Wk[i]; sWv[i] = Wv[i]; sWs[i] = Ws[i];
    }
    for (int i = threadIdx.x; i < 16; i += blockDim.x) {
        sB[i] = bq[i]; sB[16 + i] = bk[i]; sB[32 + i] = bv[i]; sB[48 + i] = bs[i];
    }
    __syncthreads();

    int lane = threadIdx.x & 31;
    int node = (blockIdx.x * blockDim.x + threadIdx.x) >> 5;
    if (node >= N_NODES) return;

    int o32 = node * 32 + lane;
    float rs = 1.0f / (g_sum[node] + EPS);
    float h  = g_agg[o32] * rs + g_s[o32];
    h = h > 0.f ? h : 0.f;

    g_agg[o32] = 0.f;
    if (lane == 0) g_sum[node] = 0.f;

    float aq = 0.f, ak = 0.f, av = 0.f, as_ = 0.f;
#pragma unroll
    for (int kk = 0; kk < 32; kk++) {
        float xk = __shfl_sync(0xffffffffu, h, kk);
        if (lane < 16) {
            aq  += xk * sWq[kk * 16 + lane];
            ak  += xk * sWk[kk * 16 + lane];
            av  += xk * sWv[kk * 16 + lane];
            as_ += xk * sWs[kk * 16 + lane];
        }
    }
    if (lane < 16) {
        int o = node * 16 + lane;
        g_q[o] = aq  + sB[lane];
        g_k[o] = ak  + sB[16 + lane];
        g_v[o] = av  + sB[32 + lane];
        g_s[o] = as_ + sB[48 + lane];
    }
}

// ---------------- finish layer 2 + output head -----------------------------
__global__ void finish2_out(const float* __restrict__ Wo, const float* __restrict__ bo,
                            float* __restrict__ out) {
    int t = blockIdx.x * blockDim.x + threadIdx.x;
    int node = t >> 4;
    int l = t & 15;
    if (node >= N_NODES) return;

    int o = node * 16 + l;
    float rs = 1.0f / (g_sum[node] + EPS);
    float h = g_agg[o] * rs + g_s[o];
    h = h > 0.f ? h : 0.f;

    float p0 = h * __ldg(Wo + l * 2 + 0);
    float p1 = h * __ldg(Wo + l * 2 + 1);
#pragma unroll
    for (int off = 1; off < 16; off <<= 1) {
        p0 += __shfl_xor_sync(0xffffffffu, p0, off);
        p1 += __shfl_xor_sync(0xffffffffu, p1, off);
    }
    if (l == 0) {
        out[node * 2 + 0] = p0 + __ldg(bo + 0);
        out[node * 2 + 1] = p1 + __ldg(bo + 1);
    }
}

extern "C" void kernel_launch(void* const* d_in, const int* in_sizes, int n_in,
                              void* d_out, int out_size) {
    const int*   ei  = (const int*)  d_in[0];
    const float* emb = (const float*)d_in[1];
    const float* Wq1 = (const float*)d_in[2];  const float* bq1 = (const float*)d_in[3];
    const float* Wk1 = (const float*)d_in[4];  const float* bk1 = (const float*)d_in[5];
    const float* Wv1 = (const float*)d_in[6];  const float* bv1 = (const float*)d_in[7];
    const float* Ws1 = (const float*)d_in[8];  const float* bs1 = (const float*)d_in[9];
    const float* Wq2 = (const float*)d_in[10]; const float* bq2 = (const float*)d_in[11];
    const float* Wk2 = (const float*)d_in[12]; const float* bk2 = (const float*)d_in[13];
    const float* Wv2 = (const float*)d_in[14]; const float* bv2 = (const float*)d_in[15];
    const float* Ws2 = (const float*)d_in[16]; const float* bs2 = (const float*)d_in[17];
    const float* Wo  = (const float*)d_in[18]; const float* bo  = (const float*)d_in[19];
    float* out = (float*)d_out;

    int E = in_sizes[0] / 2;
    int eBlocks    = (E + TPB - 1) / TPB;
    int nBlocks    = (N_NODES + TPB - 1) / TPB;
    int nodeBlocks = (N_NODES * 32 + TPB - 1) / TPB;
    int segBlocks32 = (E + 8 * 4 * 32 - 1) / (8 * 4 * 32);  // CHUNK=32
    int segBlocks16 = (E + 8 * 8 * 16 - 1) / (8 * 8 * 16);  // CHUNK=16

    // ---- sort edges by dst (once; reused by both layers) ----
    zero_deg<<<nBlocks, TPB>>>();
    hist<<<eBlocks, TPB>>>(ei, E);
    scanA<<<NB, SCAN_BLK>>>();
    scanC<<<NB, SCAN_BLK>>>();
    scatter<<<eBlocks, TPB>>>(ei, E);

    // ---- layer 1 (D=32) ----
    xform1<<<nodeBlocks, TPB>>>(emb, Wq1, bq1, Wk1, bk1, Wv1, bv1, Ws1, bs1);
    edge_seg<32, 32><<<segBlocks32, TPB>>>(E, 0.17677669529663687f);  // 1/sqrt(32)

    // ---- layer 2 (D=16) ----
    finish1_xform2<<<nodeBlocks, TPB>>>(Wq2, bq2, Wk2, bk2, Wv2, bv2, Ws2, bs2);
    edge_seg<16, 16><<<segBlocks16, TPB>>>(E, 0.25f);                 // 1/sqrt(16)

    // ---- output head ----
    finish2_out<<<(N_NODES * 16 + TPB - 1) / TPB, TPB>>>(Wo, bo, out);
}

// round 14
// speedup vs baseline: 1.0155x; 1.0155x over previous
#include <cuda_runtime.h>
#include <limits.h>

#define N_NODES 100000
#define TPB     256
#define EPS     1e-16f
#define SCAN_BLK 1024
#define NB 98   // ceil(100000/1024)
#define CHUNK 16

// ---------------- scratch (device globals; alloc-free) ----------------
__device__ float g_q[N_NODES * 32];
__device__ float g_k[N_NODES * 32];
__device__ float g_v[N_NODES * 32];
__device__ float g_s[N_NODES * 32];
__device__ float g_sum[N_NODES];
__device__ float g_agg[N_NODES * 32];
// sorted edge list (by dst)
__device__ int g_deg[N_NODES];
__device__ int g_start[N_NODES];
__device__ int g_cur[N_NODES];
__device__ int g_srcs[1700000];
__device__ int g_dsts[1700000];
__device__ int g_bsum[NB];

// ---------------- sort-by-dst build ----------------
__global__ void zero_deg() {
    int i = blockIdx.x * blockDim.x + threadIdx.x;
    if (i < N_NODES) g_deg[i] = 0;
}

__global__ void hist(const int* __restrict__ ei, int E) {
    int e = blockIdx.x * blockDim.x + threadIdx.x;
    if (e < E) atomicAdd(&g_deg[__ldg(ei + E + e)], 1);
}

__global__ void scanA() {
    __shared__ int wsum[32];
    int t = threadIdx.x, lane = t & 31, wid = t >> 5;
    int i = blockIdx.x * SCAN_BLK + t;
    int v = (i < N_NODES) ? g_deg[i] : 0;
    int incl = v;
#pragma unroll
    for (int off = 1; off < 32; off <<= 1) {
        int n = __shfl_up_sync(0xffffffffu, incl, off);
        if (lane >= off) incl += n;
    }
    if (lane == 31) wsum[wid] = incl;
    __syncthreads();
    if (wid == 0) {
        int w = wsum[lane];
#pragma unroll
        for (int off = 1; off < 32; off <<= 1) {
            int n = __shfl_up_sync(0xffffffffu, w, off);
            if (lane >= off) w += n;
        }
        wsum[lane] = w;
    }
    __syncthreads();
    int woff = (wid > 0) ? wsum[wid - 1] : 0;
    incl += woff;
    if (i < N_NODES) g_start[i] = incl - v;
    if (t == SCAN_BLK - 1) g_bsum[blockIdx.x] = incl;
}

// scanC: block offset = sum of g_bsum[j < blockIdx] via smem reduction
__global__ void scanC() {
    __shared__ int boff;
    if (threadIdx.x == 0) boff = 0;
    __syncthreads();
    if (threadIdx.x < (unsigned)blockIdx.x) atomicAdd(&boff, g_bsum[threadIdx.x]);
    __syncthreads();
    int i = blockIdx.x * SCAN_BLK + threadIdx.x;
    if (i < N_NODES) g_cur[i] = g_start[i] + boff;
}

__global__ void scatter(const int* __restrict__ ei, int E) {
    int e = blockIdx.x * blockDim.x + threadIdx.x;
    if (e >= E) return;
    int s = __ldg(ei + e);
    int d = __ldg(ei + E + e);
    int pos = atomicAdd(&g_cur[d], 1);
    g_srcs[pos] = s;
    g_dsts[pos] = d;
}

// ---------------- layer-1 transform + zero agg/sum ----------------
__global__ void xform1(const float* __restrict__ x,
                       const float* __restrict__ Wq, const float* __restrict__ bq,
                       const float* __restrict__ Wk, const float* __restrict__ bk,
                       const float* __restrict__ Wv, const float* __restrict__ bv,
                       const float* __restrict__ Ws, const float* __restrict__ bs) {
    __shared__ float sWq[32 * 32], sWk[32 * 32], sWv[32 * 32], sWs[32 * 32];
    __shared__ float sB[4 * 32];
    for (int i = threadIdx.x; i < 32 * 32; i += blockDim.x) {
        sWq[i] = Wq[i]; sWk[i] = Wk[i]; sWv[i] = Wv[i]; sWs[i] = Ws[i];
    }
    for (int i = threadIdx.x; i < 32; i += blockDim.x) {
        sB[i] = bq[i]; sB[32 + i] = bk[i]; sB[64 + i] = bv[i]; sB[96 + i] = bs[i];
    }
    __syncthreads();

    int lane = threadIdx.x & 31;
    int node = (blockIdx.x * blockDim.x + threadIdx.x) >> 5;
    if (node >= N_NODES) return;

    float xv = x[node * 32 + lane];
    float aq = 0.f, ak = 0.f, av = 0.f, as_ = 0.f;
#pragma unroll
    for (int kk = 0; kk < 32; kk++) {
        float xk = __shfl_sync(0xffffffffu, xv, kk);
        aq  += xk * sWq[kk * 32 + lane];
        ak  += xk * sWk[kk * 32 + lane];
        av  += xk * sWv[kk * 32 + lane];
        as_ += xk * sWs[kk * 32 + lane];
    }
    int o = node * 32 + lane;
    g_q[o] = aq  + sB[lane];
    g_k[o] = ak  + sB[32 + lane];
    g_v[o] = av  + sB[64 + lane];
    g_s[o] = as_ + sB[96 + lane];
    g_agg[o] = 0.f;
    if (lane == 0) g_sum[node] = 0.f;
}

// ---------------- segmented edge reduce over dst-sorted edges --------------
template <int D>
__global__ void edge_seg(int E, float rscale) {
    constexpr int G  = D / 4;
    constexpr int NG = 32 / G;
    int lane = threadIdx.x & 31;
    int wid  = threadIdx.x >> 5;
    int grp  = lane / G;
    int sub  = lane % G;

    int base = (((blockIdx.x * 8 + wid) * NG) + grp) * CHUNK;

    float4 acc = make_float4(0.f, 0.f, 0.f, 0.f);
    float  wsum = 0.f;
    int    prev_d = -1;
    float4 qv = make_float4(0.f, 0.f, 0.f, 0.f);

    for (int it = 0; it < CHUNK; it++) {
        int e = base + it;
        bool valid = (e < E);
        int d = valid ? __ldg(g_dsts + e) : prev_d;
        int s = valid ? __ldg(g_srcs + e) : 0;

        if (d != prev_d) {
            if (prev_d >= 0) {
                atomicAdd(reinterpret_cast<float4*>(g_agg + prev_d * D + sub * 4), acc);
                if (sub == 0) atomicAdd(&g_sum[prev_d], wsum);
            }
            acc = make_float4(0.f, 0.f, 0.f, 0.f);
            wsum = 0.f;
            prev_d = d;
            qv = *reinterpret_cast<const float4*>(g_q + d * D + sub * 4);
        }

        const float4 kv = *reinterpret_cast<const float4*>(g_k + s * D + sub * 4);
        float p = qv.x * kv.x + qv.y * kv.y + qv.z * kv.z + qv.w * kv.w;
#pragma unroll
        for (int off = 1; off < G; off <<= 1)
            p += __shfl_xor_sync(0xffffffffu, p, off);
        float w = valid ? __expf(fminf(p * rscale, 85.0f)) : 0.f;
        wsum += w;
        const float4 vv = *reinterpret_cast<const float4*>(g_v + s * D + sub * 4);
        acc.x += w * vv.x; acc.y += w * vv.y; acc.z += w * vv.z; acc.w += w * vv.w;
    }
    if (prev_d >= 0) {
        atomicAdd(reinterpret_cast<float4*>(g_agg + prev_d * D + sub * 4), acc);
        if (sub == 0) atomicAdd(&g_sum[prev_d], wsum);
    }
}

// ---------------- finish layer 1 + layer-2 transform + re-zero -------------
__global__ void finish1_xform2(const float* __restrict__ Wq, const float* __restrict__ bq,
                               const float* __restrict__ Wk, const float* __restrict__ bk,
                               const float* __restrict__ Wv, const float* __restrict__ bv,
                               const float* __restrict__ Ws, const float* __restrict__ bs) {
    __shared__ float sWq[32 * 16], sWk[32 * 16], sWv[32 * 16], sWs[32 * 16];
    __shared__ float sB[4 * 16];
    for (int i = threadIdx.x; i < 32 * 16; i += blockDim.x) {
        sWq[i] = Wq[i]; sWk[i] = Wk[i]; sWv[i] = Wv[i]; sWs[i] = Ws[i];
    }
    for (int i = threadIdx.x; i < 16; i += blockDim.x) {
        sB[i] = bq[i]; sB[16 + i] = bk[i]; sB[32 + i] = bv[i]; sB[48 + i] = bs[i];
    }
    __syncthreads();

    int lane = threadIdx.x & 31;
    int node = (blockIdx.x * blockDim.x + threadIdx.x) >> 5;
    if (node >= N_NODES) return;

    int o32 = node * 32 + lane;
    float rs = 1.0f / (g_sum[node] + EPS);
    float h  = g_agg[o32] * rs + g_s[o32];
    h = h > 0.f ? h : 0.f;

    g_agg[o32] = 0.f;
    if (lane == 0) g_sum[node] = 0.f;

    float aq = 0.f, ak = 0.f, av = 0.f, as_ = 0.f;
#pragma unroll
    for (int kk = 0; kk < 32; kk++) {
        float xk = __shfl_sync(0xffffffffu, h, kk);
        if (lane < 16) {
            aq  += xk * sWq[kk * 16 + lane];
            ak  += xk * sWk[kk * 16 + lane];
            av  += xk * sWv[kk * 16 + lane];
            as_ += xk * sWs[kk * 16 + lane];
        }
    }
    if (lane < 16) {
        int o = node * 16 + lane;
        g_q[o] = aq  + sB[lane];
        g_k[o] = ak  + sB[16 + lane];
        g_v[o] = av  + sB[32 + lane];
        g_s[o] = as_ + sB[48 + lane];
    }
}

// ---------------- finish layer 2 + output head -----------------------------
__global__ void finish2_out(const float* __restrict__ Wo, const float* __restrict__ bo,
                            float* __restrict__ out) {
    int t = blockIdx.x * blockDim.x + threadIdx.x;
    int node = t >> 4;
    int l = t & 15;
    if (node >= N_NODES) return;

    int o = node * 16 + l;
    float rs = 1.0f / (g_sum[node] + EPS);
    float h = g_agg[o] * rs + g_s[o];
    h = h > 0.f ? h : 0.f;

    float p0 = h * __ldg(Wo + l * 2 + 0);
    float p1 = h * __ldg(Wo + l * 2 + 1);
#pragma unroll
    for (int off = 1; off < 16; off <<= 1) {
        p0 += __shfl_xor_sync(0xffffffffu, p0, off);
        p1 += __shfl_xor_sync(0xffffffffu, p1, off);
    }
    if (l == 0) {
        out[node * 2 + 0] = p0 + __ldg(bo + 0);
        out[node * 2 + 1] = p1 + __ldg(bo + 1);
    }
}

extern "C" void kernel_launch(void* const* d_in, const int* in_sizes, int n_in,
                              void* d_out, int out_size) {
    const int*   ei  = (const int*)  d_in[0];
    const float* emb = (const float*)d_in[1];
    const float* Wq1 = (const float*)d_in[2];  const float* bq1 = (const float*)d_in[3];
    const float* Wk1 = (const float*)d_in[4];  const float* bk1 = (const float*)d_in[5];
    const float* Wv1 = (const float*)d_in[6];  const float* bv1 = (const float*)d_in[7];
    const float* Ws1 = (const float*)d_in[8];  const float* bs1 = (const float*)d_in[9];
    const float* Wq2 = (const float*)d_in[10]; const float* bq2 = (const float*)d_in[11];
    const float* Wk2 = (const float*)d_in[12]; const float* bk2 = (const float*)d_in[13];
    const float* Wv2 = (const float*)d_in[14]; const float* bv2 = (const float*)d_in[15];
    const float* Ws2 = (const float*)d_in[16]; const float* bs2 = (const float*)d_in[17];
    const float* Wo  = (const float*)d_in[18]; const float* bo  = (const float*)d_in[19];
    float* out = (float*)d_out;

    int E = in_sizes[0] / 2;
    int eBlocks    = (E + TPB - 1) / TPB;
    int nBlocks    = (N_NODES + TPB - 1) / TPB;
    int nodeBlocks = (N_NODES * 32 + TPB - 1) / TPB;
    int segBlocks32 = (E + 8 * 4 * CHUNK - 1) / (8 * 4 * CHUNK);
    int segBlocks16 = (E + 8 * 8 * CHUNK - 1) / (8 * 8 * CHUNK);

    // Fork a side stream so xform1 (independent node transform) overlaps the
    // edge-sort build.  Standard capture-legal fork/join via events; stream
    // and events are host objects (no device memory) and are deliberately not
    // destroyed here to avoid mid-capture destruction hazards.
    cudaStream_t s2;
    cudaEvent_t evFork, evJoin;
    cudaStreamCreateWithFlags(&s2, cudaStreamNonBlocking);
    cudaEventCreateWithFlags(&evFork, cudaEventDisableTiming);
    cudaEventCreateWithFlags(&evJoin, cudaEventDisableTiming);

    cudaEventRecord(evFork, 0);
    cudaStreamWaitEvent(s2, evFork, 0);

    // side stream: layer-1 node transform (independent of build)
    xform1<<<nodeBlocks, TPB, 0, s2>>>(emb, Wq1, bq1, Wk1, bk1, Wv1, bv1, Ws1, bs1);
    cudaEventRecord(evJoin, s2);

    // main stream: sort edges by dst
    zero_deg<<<nBlocks, TPB>>>();
    hist<<<eBlocks, TPB>>>(ei, E);
    scanA<<<NB, SCAN_BLK>>>();
    scanC<<<NB, SCAN_BLK>>>();
    scatter<<<eBlocks, TPB>>>(ei, E);

    // join: edge aggregation needs both
    cudaStreamWaitEvent(0, evJoin, 0);

    // ---- layer 1 (D=32) ----
    edge_seg<32><<<segBlocks32, TPB>>>(E, 0.17677669529663687f);  // 1/sqrt(32)

    // ---- layer 2 (D=16) ----
    finish1_xform2<<<nodeBlocks, TPB>>>(Wq2, bq2, Wk2, bk2, Wv2, bv2, Ws2, bs2);
    edge_seg<16><<<segBlocks16, TPB>>>(E, 0.25f);                 // 1/sqrt(16)

    // ---- output head ----
    finish2_out<<<(N_NODES * 16 + TPB - 1) / TPB, TPB>>>(Wo, bo, out);
}